// round 1
// baseline (speedup 1.0000x reference)
#include <cuda_runtime.h>
#include <cstdint>

// FSMN depthwise strided FIR on GB300.
// out[b,t,d] = sum_{i=0..19} filt[i,d]    * x[b, t-(20-i)*2, d]
//            +               filt[20,d]   * x[b, t, d]
//            + sum_{j=0..19} filt[21+j,d] * x[b, t+1+2j, d]
// with zero padding outside [0,T).
//
// Parity decomposition: outputs t0, t0+2, ..., t0+14 (8 same-parity outputs)
// read two DENSE streams:
//   A[u] = x[t0-40+2u]  (u=0..27, taps fL[0..20] = filt[0..20])
//   B[v] = x[t0+1+2v]   (v=0..26, taps fR[0..19] = filt[21..40])
// Rotating 8-deep register window => 55 loads per 8 outputs (vs 328 naive).
// Packed fma.rn.f32x2 halves the FMA-pipe instruction count (ptxas will not
// auto-fuse two fmaf into FFMA2 — PTX is required).

#define B_ 32
#define T_ 2000
#define D_ 512
#define DP 256          // d-pairs (float2 lanes)
#define RT 8            // outputs per parity chunk
#define SEG 5           // 16-wide t-bases per block
// T_ = 2000 = 125 bases * 16; grid.x = 125/SEG = 25

__device__ __forceinline__ uint64_t f2fma(uint64_t a, uint64_t b, uint64_t c) {
    uint64_t r;
    asm("fma.rn.f32x2 %0, %1, %2, %3;" : "=l"(r) : "l"(a), "l"(b), "l"(c));
    return r;
}

__global__ __launch_bounds__(256)
void fsmn_kernel(const float* __restrict__ x,
                 const float* __restrict__ filt,
                 float* __restrict__ out)
{
    const int dp  = threadIdx.x;      // d-pair index 0..255
    const int b   = blockIdx.y;
    const int seg = blockIdx.x;

    // Filter taps for this channel pair, held in registers for the whole block.
    const uint64_t* __restrict__ f2 = reinterpret_cast<const uint64_t*>(filt);
    uint64_t fL[21], fR[20];
#pragma unroll
    for (int i = 0; i < 21; ++i) fL[i] = f2[i * DP + dp];
#pragma unroll
    for (int j = 0; j < 20; ++j) fR[j] = f2[(21 + j) * DP + dp];

    const uint64_t* __restrict__ xb =
        reinterpret_cast<const uint64_t*>(x) + (size_t)b * T_ * DP + dp;
    uint64_t* __restrict__ ob =
        reinterpret_cast<uint64_t*>(out) + (size_t)b * T_ * DP + dp;

    for (int s = 0; s < SEG; ++s) {
        const int tb = (seg * SEG + s) * (2 * RT);
        // Inputs touched by both parity chunks span [tb-40, tb+54].
        const bool fast = (tb >= 40) && (tb + 54 < T_);

#pragma unroll
        for (int par = 0; par < 2; ++par) {
            const int t0 = tb + par;

            uint64_t acc[RT];
#pragma unroll
            for (int r = 0; r < RT; ++r) acc[r] = 0ull;

            uint64_t w[RT];

            // ---------- A stream: taps fL[0..20] over x[t0-40+2u] ----------
            {
                const int tA = t0 - 40;
                if (fast) {
#pragma unroll
                    for (int u = 0; u < RT; ++u)
                        w[u] = xb[(size_t)(tA + 2 * u) * DP];
#pragma unroll
                    for (int c = 0; c < 21; ++c) {
#pragma unroll
                        for (int r = 0; r < RT; ++r)
                            acc[r] = f2fma(fL[c], w[(c + r) & (RT - 1)], acc[r]);
                        if (c < 20)
                            w[c & (RT - 1)] = xb[(size_t)(tA + 2 * (c + RT)) * DP];
                    }
                } else {
#pragma unroll
                    for (int u = 0; u < RT; ++u) {
                        const int ti = tA + 2 * u;
                        w[u] = (ti >= 0 && ti < T_) ? xb[(size_t)ti * DP] : 0ull;
                    }
#pragma unroll
                    for (int c = 0; c < 21; ++c) {
#pragma unroll
                        for (int r = 0; r < RT; ++r)
                            acc[r] = f2fma(fL[c], w[(c + r) & (RT - 1)], acc[r]);
                        if (c < 20) {
                            const int ti = tA + 2 * (c + RT);
                            w[c & (RT - 1)] =
                                (ti >= 0 && ti < T_) ? xb[(size_t)ti * DP] : 0ull;
                        }
                    }
                }
            }

            // ---------- B stream: taps fR[0..19] over x[t0+1+2v] ----------
            {
                const int tB = t0 + 1;
                if (fast) {
#pragma unroll
                    for (int u = 0; u < RT; ++u)
                        w[u] = xb[(size_t)(tB + 2 * u) * DP];
#pragma unroll
                    for (int c = 0; c < 20; ++c) {
#pragma unroll
                        for (int r = 0; r < RT; ++r)
                            acc[r] = f2fma(fR[c], w[(c + r) & (RT - 1)], acc[r]);
                        if (c < 19)
                            w[c & (RT - 1)] = xb[(size_t)(tB + 2 * (c + RT)) * DP];
                    }
                } else {
#pragma unroll
                    for (int u = 0; u < RT; ++u) {
                        const int ti = tB + 2 * u;
                        w[u] = (ti >= 0 && ti < T_) ? xb[(size_t)ti * DP] : 0ull;
                    }
#pragma unroll
                    for (int c = 0; c < 20; ++c) {
#pragma unroll
                        for (int r = 0; r < RT; ++r)
                            acc[r] = f2fma(fR[c], w[(c + r) & (RT - 1)], acc[r]);
                        if (c < 19) {
                            const int ti = tB + 2 * (c + RT);
                            w[c & (RT - 1)] =
                                (ti >= 0 && ti < T_) ? xb[(size_t)ti * DP] : 0ull;
                        }
                    }
                }
            }

            // ---------- store 8 outputs (always in-bounds: t0+14 <= 1999) ----------
#pragma unroll
            for (int r = 0; r < RT; ++r)
                ob[(size_t)(t0 + 2 * r) * DP] = acc[r];
        }
    }
}

extern "C" void kernel_launch(void* const* d_in, const int* in_sizes, int n_in,
                              void* d_out, int out_size)
{
    const float* x    = (const float*)d_in[0];   // [32, 2000, 512] f32
    const float* filt = (const float*)d_in[1];   // [41, 512] f32
    float* out        = (float*)d_out;           // [32, 2000, 512] f32

    dim3 grid(25, B_);   // 25 t-segments x 32 batch
    fsmn_kernel<<<grid, 256>>>(x, filt, out);
}